// round 13
// baseline (speedup 1.0000x reference)
#include <cuda_runtime.h>

// Problem constants (fixed by the dataset)
#define BATCH 32
#define NA    3
#define GH    80
#define GW    80
#define NB    50
#define NCLS  1
#define HW    (GH*GW)                 // 6400
#define THREADS 256

// 16x16 spatial tiles; one block = one tile x ALL 3 anchors (768 cells, 3/thread)
#define TW 16
#define TH 16
#define TILES_X (GW/TW)               // 5
#define TILES_Y (GH/TH)               // 5
#define TILES   (TILES_X*TILES_Y)     // 25
#define TOTAL_BLOCKS (BATCH*TILES)    // 800
#define NBANDS 4                      // 4-row y-bands within the tile
#define NBANK  16                     // accumulator banks (contention spread)

// Banked global accumulators: box, weighted_obj, cls (double) + n_pos, noobj_cnt (int)
__device__ double g_accF[NBANK][3];
__device__ int    g_npos[NBANK];
__device__ int    g_nobj[NBANK];
__device__ int    g_count = 0;

__device__ __forceinline__ float tanh_fast(float x) {
    float t;
    asm("tanh.approx.f32 %0, %1;" : "=f"(t) : "f"(x));
    return t;
}

__global__ __launch_bounds__(THREADS, 6) void yolo_fused_kernel(
    const float* __restrict__ head,
    const float* __restrict__ boxes,
    const float* __restrict__ anchors,
    const int*   __restrict__ labels,
    float* __restrict__ out)
{
    __shared__ float4 s_bl[NBANDS][2][32];  // band GT xyxy lists (sentinel-backfilled)
    __shared__ float  s_ba[NBANDS][2][32];  // band GT area/3
    __shared__ int    s_bc[NBANDS][2];      // band list counts
    __shared__ int    s_mpk[64];            // match cand packed (anc<<22)|(gj<<14)|(gi<<6)|n
    __shared__ int    s_mcnt[2];
    __shared__ float  s_redF[8][3];
    __shared__ int    s_redI[8][2];

    const int b    = blockIdx.y;
    const int t    = blockIdx.x;                 // 0..24 spatial tile
    const int tid  = threadIdx.x;
    const int th   = t / TILES_X;
    const int tw   = t - th * TILES_X;
    const int w0   = tw * TW;
    const int h0   = th * TH;
    const int lane = tid & 31, warp = tid >> 5;

    // --- hoisted boxes load (warps 0-1): issued FIRST so its latency overlaps
    //     the head loads below instead of sitting on the barrier path ---
    const bool prepw = tid < 64;
    const bool valid = tid < NB;
    float4 g = make_float4(4.0f, 4.0f, 0.0f, 0.0f);
    if (valid) g = ((const float4*)boxes)[b * NB + tid];

    // --- issue ALL head loads (overlaps boxes load + prep math) ---
    const int wx    = w0 + (tid & (TW-1));
    const int hy    = h0 + (tid >> 4);
    const int rem   = hy * GW + wx;
    const int base0 = (b * NA) * (6 * HW) + rem;     // fits in int32

    float xo[NA], hx[NA], hyv[NA], hw[NA], hh[NA];
    #pragma unroll
    for (int a = 0; a < NA; a++) {
        const int base = base0 + a * (6 * HW);
        xo[a]  = head[base];
        hx[a]  = head[base +     HW];
        hyv[a] = head[base + 2 * HW];
        hw[a]  = head[base + 3 * HW];
        hh[a]  = head[base + 4 * HW];
    }

    // --- per-GT prep: warps 0-1 build 4 band lists + match list.
    //     Write-all-slots compaction: survivors at the front, sentinels behind,
    //     every slot written by exactly one lane -> NO pre-fill, NO barrier. ---
    if (prepw) {
        const float gx1 = g.x - 0.5f * g.z, gy1 = g.y - 0.5f * g.w;
        const float gx2 = g.x + 0.5f * g.z, gy2 = g.y + 0.5f * g.w;
        const float aG3 = g.z * g.w * (1.0f/3.0f);
        const int seg = warp;

        // common x window (iou>0.5 => pred center strictly inside gt box)
        const float bxLo = ((float)w0        - 0.1f) * (1.0f/GW) - 1e-4f;
        const float bxHi = ((float)(w0+TW-1) + 1.1f) * (1.0f/GW) + 1e-4f;
        const bool xov = valid && gx1 < bxHi && gx2 > bxLo;

        #pragma unroll
        for (int band = 0; band < NBANDS; band++) {
            const int r0 = h0 + band * 4;
            const float byLo = ((float)r0       - 0.1f) * (1.0f/GH) - 1e-4f;
            const float byHi = ((float)(r0 + 3) + 1.1f) * (1.0f/GH) + 1e-4f;
            const bool p = xov && gy1 < byHi && gy2 > byLo;
            const unsigned bal = __ballot_sync(0xFFFFFFFFu, p);
            const int cnt = __popc(bal);
            const unsigned below = (1u << lane) - 1u;
            // survivors compacted at front; non-survivors backfill sentinels
            const int pos = p ? __popc(bal & below)
                              : cnt + __popc((~bal) & below);
            if (p) {
                s_bl[band][seg][pos] = make_float4(gx1, gy1, gx2, gy2);
                s_ba[band][seg][pos] = aG3;
            } else {
                s_bl[band][seg][pos] = make_float4(9.0f, 9.0f, 9.0f, 9.0f);
                s_ba[band][seg][pos] = 1.0f;
            }
            if (lane == 0) s_bc[band][seg] = cnt;
        }

        // match candidates (cell assignment), packed single word
        const int gi = (int)floorf(g.x * (float)GW);
        const int gj = (int)floorf(g.y * (float)GH);
        int anc = 0; float best = -1.0f;
        #pragma unroll
        for (int k = 0; k < NA; k++) {
            const float aw = anchors[2*k], ah = anchors[2*k+1];
            const float it = fminf(g.z, aw) * fminf(g.w, ah);
            const float un = g.z * g.w + aw * ah - it;
            const float r  = it / un;
            if (r > best) { best = r; anc = k; }
        }
        const bool mpred = valid && gi >= w0 && gi < w0 + TW
                                 && gj >= h0 && gj < h0 + TH;
        const unsigned mb = __ballot_sync(0xFFFFFFFFu, mpred);
        if (mpred) {
            const int pos = seg * 32 + __popc(mb & ((1u << lane) - 1u));
            s_mpk[pos] = (anc << 22) | (gj << 14) | (gi << 6) | tid;
        }
        if (lane == 0) s_mcnt[seg] = __popc(mb);
    }

    // --- decode pred boxes: leaky-sigmoid via tanh (1.2*sig(x)-0.1 = 0.6*tanh(x/2)+0.5) ---
    float px1[NA], py1[NA], px2[NA], py2[NA], aP3[NA];
    #pragma unroll
    for (int a = 0; a < NA; a++) {
        const float tx = tanh_fast(0.5f * hx[a]);
        const float ty = tanh_fast(0.5f * hyv[a]);
        const float bx = (0.6f * tx + 0.5f + (float)wx) * (1.0f/GW);
        const float by = (0.6f * ty + 0.5f + (float)hy) * (1.0f/GH);
        const float bw = __expf(hw[a]) * anchors[2*a];
        const float bh = __expf(hh[a]) * anchors[2*a+1];
        px1[a] = bx - 0.5f*bw; py1[a] = by - 0.5f*bh;
        px2[a] = bx + 0.5f*bw; py2[a] = by + 0.5f*bh;
        aP3[a] = bw * bh * (1.0f/3.0f);
    }
    __syncthreads();   // ONLY pre-reduction barrier: prep lists ready

    // --- noobj scan: this warp's 4-row band list, unconditional, unroll-2 ---
    bool ign[NA] = {false, false, false};
    {
        const int band = warp >> 1;   // warp covers rows h0+2*warp..+1 -> band = warp/2
        #pragma unroll
        for (int s = 0; s < 2; s++) {
            const int c2 = (s_bc[band][s] + 1) & ~1;
            for (int k = 0; k < c2; k += 2) {
                const float4 g0  = s_bl[band][s][k];
                const float4 g1  = s_bl[band][s][k + 1];
                const float aG30 = s_ba[band][s][k];
                const float aG31 = s_ba[band][s][k + 1];
                #pragma unroll
                for (int a = 0; a < NA; a++) {
                    const float ox0 = fminf(px2[a], g0.z) - fmaxf(px1[a], g0.x);
                    const float oy0 = fminf(py2[a], g0.w) - fmaxf(py1[a], g0.y);
                    const float ox1 = fminf(px2[a], g1.z) - fmaxf(px1[a], g1.x);
                    const float oy1 = fminf(py2[a], g1.w) - fmaxf(py1[a], g1.y);
                    const bool i0 = fmaxf(ox0, 0.0f) * fmaxf(oy0, 0.0f) > aG30 + aP3[a];
                    const bool i1 = fmaxf(ox1, 0.0f) * fmaxf(oy1, 0.0f) > aG31 + aP3[a];
                    ign[a] = ign[a] || i0 || i1;
                }
            }
        }
    }

    // --- single match scan for all 3 anchors (last-write-wins == max n) ---
    int bestA[NA] = {-1, -1, -1};
    {
        const int ij = (hy << 8) | wx;
        #pragma unroll
        for (int s = 0; s < 2; s++) {
            const int c = s_mcnt[s];
            for (int k = 0; k < c; k++) {
                const int pk = s_mpk[s*32 + k];
                if (((pk >> 6) & 0xFFFF) == ij) {
                    const int anc = pk >> 22;
                    const int n   = pk & 63;
                    if (anc == 0)      bestA[0] = max(bestA[0], n);
                    else if (anc == 1) bestA[1] = max(bestA[1], n);
                    else               bestA[2] = max(bestA[2], n);
                }
            }
        }
    }

    // --- per-anchor accumulation: 3 float channels + 2 ballot-counted ints ---
    // f0=box, f1=1.5*obj+0.5*noobj_bce, f2=cls
    float vals[3] = {0.0f, 0.0f, 0.0f};
    int np = 0, nn = 0;   // warp totals via popc (identical across lanes)
    #pragma unroll
    for (int a = 0; a < NA; a++) {
        const bool matched = bestA[a] >= 0;
        const float noobj = ign[a] ? 0.0f : 1.0f;

        // exact counts via ballots (replaces 2 float reduction channels)
        const unsigned bm = __ballot_sync(0xFFFFFFFFu, matched);
        const unsigned bn = __ballot_sync(0xFFFFFFFFu, !ign[a]);
        np += __popc(bm);
        nn += __popc(bn);

        // softplus: -log(sigmoid(x)) = log(1+e^-x); -log(1-sigmoid(x)) = x + log(1+e^-x)
        const float l = __logf(1.0f + __expf(-xo[a]));

        if (matched) {
            const int bestN = bestA[a];
            const float bceP1 = fminf(l, 100.0f);
            vals[1] += 1.5f * bceP1 + 0.5f * noobj * bceP1;
            // cls bce (lazy load + exp-based sigmoid for log accuracy)
            const float xCls = head[base0 + a * (6 * HW) + 5 * HW];
            const float pCls = __fdividef(1.0f, 1.0f + __expf(-xCls));
            const int   labN = labels[b * NB + bestN];
            const float tC   = (labN == 0) ? 1.0f : 0.0f;
            const float lc1  = fmaxf(__logf(pCls),        -100.0f);
            const float lc0  = fmaxf(__logf(1.0f - pCls), -100.0f);
            vals[2] += -(tC * lc1 + (1.0f - tC) * lc0);
            // ciou(pred, target); GT box re-loaded from gmem (rare path, L1/L2-hot)
            const float4 gb = ((const float4*)boxes)[b * NB + bestN];
            const float tx1 = gb.x - 0.5f*gb.z, ty1 = gb.y - 0.5f*gb.w;
            const float tx2 = gb.x + 0.5f*gb.z, ty2 = gb.y + 0.5f*gb.w;
            const float bw = px2[a] - px1[a], bh = py2[a] - py1[a];
            const float bx = 0.5f * (px1[a] + px2[a]);
            const float by = 0.5f * (py1[a] + py2[a]);
            const float imx = fmaxf(px1[a], tx1), imy = fmaxf(py1[a], ty1);
            const float iMx = fminf(px2[a], tx2), iMy = fminf(py2[a], ty2);
            const float iw = fmaxf(iMx - imx, 0.0f), ihh = fmaxf(iMy - imy, 0.0f);
            const float inter = iw * ihh;
            const float uni = bw * bh + gb.z * gb.w - inter;
            const float iou = inter / fmaxf(uni, 1e-6f);
            const float d   = fabsf(bx - gb.x) + fabsf(by - gb.y);
            const float ex1 = fminf(px1[a], tx1), ey1 = fminf(py1[a], ty1);
            const float ex2 = fmaxf(px2[a], tx2), ey2 = fmaxf(py2[a], ty2);
            const float cc  = fabsf(ex2 - ex1) + fabsf(ey2 - ey1);
            const float dis = d / fmaxf(cc, 1e-6f);
            const float a1  = atanf(bw / fmaxf(bh, 1e-6f));
            const float a2  = atanf(gb.z / fmaxf(gb.w, 1e-6f));
            const float PIc = 3.1415926f;
            const float vv  = (4.0f / (PIc * PIc)) * fabsf(a1 - a2);
            const float al  = vv / fmaxf(1.0f - iou + vv, 1e-6f);
            vals[0] += 1.0f - iou + dis + al * vv;
        } else {
            vals[1] += 0.5f * noobj * fminf(xo[a] + l, 100.0f);   // bce(p,0)
        }
    }

    // --- block reduction: 3 float channels (shuffle) + 2 int (lane0 only) ---
    #pragma unroll
    for (int off = 16; off > 0; off >>= 1) {
        #pragma unroll
        for (int j = 0; j < 3; j++)
            vals[j] += __shfl_down_sync(0xFFFFFFFFu, vals[j], off);
    }
    if (lane == 0) {
        #pragma unroll
        for (int j = 0; j < 3; j++) s_redF[warp][j] = vals[j];
        s_redI[warp][0] = np;
        s_redI[warp][1] = nn;
    }
    __syncthreads();
    if (warp == 0) {
        float r[3];
        #pragma unroll
        for (int j = 0; j < 3; j++) r[j] = (lane < 8) ? s_redF[lane][j] : 0.0f;
        #pragma unroll
        for (int off = 4; off > 0; off >>= 1) {
            #pragma unroll
            for (int j = 0; j < 3; j++)
                r[j] += __shfl_down_sync(0xFFFFFFFFu, r[j], off);
        }

        const int bank = (b * TILES + t) & (NBANK - 1);
        int isLast = 0;
        if (lane == 0) {
            int npos_b = 0, nobj_b = 0;
            #pragma unroll
            for (int w = 0; w < 8; w++) { npos_b += s_redI[w][0]; nobj_b += s_redI[w][1]; }
            #pragma unroll
            for (int j = 0; j < 3; j++) atomicAdd(&g_accF[bank][j], (double)r[j]);
            atomicAdd(&g_npos[bank], npos_b);
            atomicAdd(&g_nobj[bank], nobj_b);
            __threadfence();
            const int old = atomicAdd(&g_count, 1);
            isLast = (old == TOTAL_BLOCKS - 1);
        }
        isLast = __shfl_sync(0xFFFFFFFFu, isLast, 0);
        if (isLast) {
            __threadfence();
            // lanes 0..15 each read one bank; shfl-reduce 16 -> 1
            double d0 = 0.0, d1 = 0.0, d2 = 0.0;
            int    i0 = 0, i1 = 0;
            if (lane < NBANK) {
                d0 = g_accF[lane][0]; d1 = g_accF[lane][1]; d2 = g_accF[lane][2];
                i0 = g_npos[lane];    i1 = g_nobj[lane];
            }
            #pragma unroll
            for (int off = 8; off > 0; off >>= 1) {
                d0 += __shfl_down_sync(0xFFFFFFFFu, d0, off);
                d1 += __shfl_down_sync(0xFFFFFFFFu, d1, off);
                d2 += __shfl_down_sync(0xFFFFFFFFu, d2, off);
                i0 += __shfl_down_sync(0xFFFFFFFFu, i0, off);
                i1 += __shfl_down_sync(0xFFFFFFFFu, i1, off);
            }
            if (lane == 0) {
                const double npos = (double)i0;
                const double nobj = (double)i1;
                out[0] = (float)(0.05 * d0 / npos);
                out[1] = (float)(d1 / (npos + nobj) + 0.5 * d2 / (npos * (double)NCLS));
                g_count = 0;   // reset for next graph replay
            }
            // reset banks for next graph replay
            if (lane < NBANK) {
                g_accF[lane][0] = 0.0; g_accF[lane][1] = 0.0; g_accF[lane][2] = 0.0;
                g_npos[lane] = 0;      g_nobj[lane] = 0;
            }
        }
    }
}

extern "C" void kernel_launch(void* const* d_in, const int* in_sizes, int n_in,
                              void* d_out, int out_size) {
    const float* head    = (const float*)d_in[0];
    const float* boxes   = (const float*)d_in[1];
    const float* anchors = (const float*)d_in[2];
    const int*   labels  = (const int*)d_in[3];
    (void)in_sizes; (void)n_in; (void)out_size;

    dim3 grid(TILES, BATCH);
    yolo_fused_kernel<<<grid, THREADS>>>(head, boxes, anchors, labels, (float*)d_out);
}

// round 14
// speedup vs baseline: 1.0667x; 1.0667x over previous
#include <cuda_runtime.h>

// Problem constants (fixed by the dataset)
#define BATCH 32
#define NA    3
#define GH    80
#define GW    80
#define NB    50
#define NCLS  1
#define HW    (GH*GW)                 // 6400
#define THREADS 256

// 16x16 spatial tiles; one block = one tile x ALL 3 anchors (768 cells, 3/thread)
#define TW 16
#define TH 16
#define TILES_X (GW/TW)               // 5
#define TILES_Y (GH/TH)               // 5
#define TILES   (TILES_X*TILES_Y)     // 25
#define TOTAL_BLOCKS (BATCH*TILES)    // 800
#define NBANDS 4                      // 4-row y-bands within the tile

// Global accumulators: box, weighted_obj, cls (double) + n_pos, noobj_cnt (int)
__device__ double g_accF[3] = {0.0, 0.0, 0.0};
__device__ int    g_npos = 0;
__device__ int    g_nobj = 0;
__device__ int    g_count = 0;

__device__ __forceinline__ float tanh_fast(float x) {
    float t;
    asm("tanh.approx.f32 %0, %1;" : "=f"(t) : "f"(x));
    return t;
}

__global__ __launch_bounds__(THREADS, 6) void yolo_fused_kernel(
    const float* __restrict__ head,
    const float* __restrict__ boxes,
    const float* __restrict__ anchors,
    const int*   __restrict__ labels,
    float* __restrict__ out)
{
    __shared__ float4 s_bl[NBANDS][2][32];  // band GT xyxy lists (sentinel-backfilled)
    __shared__ float  s_ba[NBANDS][2][32];  // band GT area/3
    __shared__ int    s_bc[NBANDS][2];      // band list counts
    __shared__ int    s_mpk[64];            // match cand packed (anc<<22)|(gj<<14)|(gi<<6)|n
    __shared__ int    s_mcnt[2];
    __shared__ float  s_redF[8][3];
    __shared__ int    s_redI[8][2];

    const int b    = blockIdx.y;
    const int t    = blockIdx.x;                 // 0..24 spatial tile
    const int tid  = threadIdx.x;
    const int th   = t / TILES_X;
    const int tw   = t - th * TILES_X;
    const int w0   = tw * TW;
    const int h0   = th * TH;
    const int lane = tid & 31, warp = tid >> 5;

    // --- hoisted boxes load (warps 0-1): issued FIRST so its latency overlaps
    //     the head loads below instead of sitting on the barrier path ---
    const bool prepw = tid < 64;
    const bool valid = tid < NB;
    float4 g = make_float4(4.0f, 4.0f, 0.0f, 0.0f);
    if (valid) g = ((const float4*)boxes)[b * NB + tid];

    // --- issue ALL head loads (overlaps boxes load + prep math) ---
    const int wx    = w0 + (tid & (TW-1));
    const int hy    = h0 + (tid >> 4);
    const int rem   = hy * GW + wx;
    const int base0 = (b * NA) * (6 * HW) + rem;     // fits in int32

    float xo[NA], hx[NA], hyv[NA], hw[NA], hh[NA];
    #pragma unroll
    for (int a = 0; a < NA; a++) {
        const int base = base0 + a * (6 * HW);
        xo[a]  = head[base];
        hx[a]  = head[base +     HW];
        hyv[a] = head[base + 2 * HW];
        hw[a]  = head[base + 3 * HW];
        hh[a]  = head[base + 4 * HW];
    }

    // --- per-GT prep: warps 0-1 build 4 band lists + match list.
    //     Write-all-slots compaction: survivors at the front, sentinels behind,
    //     every slot written by exactly one lane -> NO pre-fill, NO barrier. ---
    if (prepw) {
        const float gx1 = g.x - 0.5f * g.z, gy1 = g.y - 0.5f * g.w;
        const float gx2 = g.x + 0.5f * g.z, gy2 = g.y + 0.5f * g.w;
        const float aG3 = g.z * g.w * (1.0f/3.0f);
        const int seg = warp;

        // common x window (iou>0.5 => pred center strictly inside gt box)
        const float bxLo = ((float)w0        - 0.1f) * (1.0f/GW) - 1e-4f;
        const float bxHi = ((float)(w0+TW-1) + 1.1f) * (1.0f/GW) + 1e-4f;
        const bool xov = valid && gx1 < bxHi && gx2 > bxLo;

        #pragma unroll
        for (int band = 0; band < NBANDS; band++) {
            const int r0 = h0 + band * 4;
            const float byLo = ((float)r0       - 0.1f) * (1.0f/GH) - 1e-4f;
            const float byHi = ((float)(r0 + 3) + 1.1f) * (1.0f/GH) + 1e-4f;
            const bool p = xov && gy1 < byHi && gy2 > byLo;
            const unsigned bal = __ballot_sync(0xFFFFFFFFu, p);
            const int cnt = __popc(bal);
            const unsigned below = (1u << lane) - 1u;
            // survivors compacted at front; non-survivors backfill sentinels
            const int pos = p ? __popc(bal & below)
                              : cnt + __popc((~bal) & below);
            if (p) {
                s_bl[band][seg][pos] = make_float4(gx1, gy1, gx2, gy2);
                s_ba[band][seg][pos] = aG3;
            } else {
                s_bl[band][seg][pos] = make_float4(9.0f, 9.0f, 9.0f, 9.0f);
                s_ba[band][seg][pos] = 1.0f;
            }
            if (lane == 0) s_bc[band][seg] = cnt;
        }

        // match candidates (cell assignment), packed single word
        const int gi = (int)floorf(g.x * (float)GW);
        const int gj = (int)floorf(g.y * (float)GH);
        int anc = 0; float best = -1.0f;
        #pragma unroll
        for (int k = 0; k < NA; k++) {
            const float aw = anchors[2*k], ah = anchors[2*k+1];
            const float it = fminf(g.z, aw) * fminf(g.w, ah);
            const float un = g.z * g.w + aw * ah - it;
            const float r  = it / un;
            if (r > best) { best = r; anc = k; }
        }
        const bool mpred = valid && gi >= w0 && gi < w0 + TW
                                 && gj >= h0 && gj < h0 + TH;
        const unsigned mb = __ballot_sync(0xFFFFFFFFu, mpred);
        if (mpred) {
            const int pos = seg * 32 + __popc(mb & ((1u << lane) - 1u));
            s_mpk[pos] = (anc << 22) | (gj << 14) | (gi << 6) | tid;
        }
        if (lane == 0) s_mcnt[seg] = __popc(mb);
    }

    // --- decode pred boxes: leaky-sigmoid via tanh (1.2*sig(x)-0.1 = 0.6*tanh(x/2)+0.5) ---
    float px1[NA], py1[NA], px2[NA], py2[NA], aP3[NA];
    #pragma unroll
    for (int a = 0; a < NA; a++) {
        const float tx = tanh_fast(0.5f * hx[a]);
        const float ty = tanh_fast(0.5f * hyv[a]);
        const float bx = (0.6f * tx + 0.5f + (float)wx) * (1.0f/GW);
        const float by = (0.6f * ty + 0.5f + (float)hy) * (1.0f/GH);
        const float bw = __expf(hw[a]) * anchors[2*a];
        const float bh = __expf(hh[a]) * anchors[2*a+1];
        px1[a] = bx - 0.5f*bw; py1[a] = by - 0.5f*bh;
        px2[a] = bx + 0.5f*bw; py2[a] = by + 0.5f*bh;
        aP3[a] = bw * bh * (1.0f/3.0f);
    }
    __syncthreads();   // ONLY pre-reduction barrier: prep lists ready

    // --- noobj scan: this warp's 4-row band list, unconditional, unroll-2 ---
    bool ign[NA] = {false, false, false};
    {
        const int band = warp >> 1;   // warp covers rows h0+2*warp..+1 -> band = warp/2
        #pragma unroll
        for (int s = 0; s < 2; s++) {
            const int c2 = (s_bc[band][s] + 1) & ~1;
            for (int k = 0; k < c2; k += 2) {
                const float4 g0  = s_bl[band][s][k];
                const float4 g1  = s_bl[band][s][k + 1];
                const float aG30 = s_ba[band][s][k];
                const float aG31 = s_ba[band][s][k + 1];
                #pragma unroll
                for (int a = 0; a < NA; a++) {
                    const float ox0 = fminf(px2[a], g0.z) - fmaxf(px1[a], g0.x);
                    const float oy0 = fminf(py2[a], g0.w) - fmaxf(py1[a], g0.y);
                    const float ox1 = fminf(px2[a], g1.z) - fmaxf(px1[a], g1.x);
                    const float oy1 = fminf(py2[a], g1.w) - fmaxf(py1[a], g1.y);
                    const bool i0 = fmaxf(ox0, 0.0f) * fmaxf(oy0, 0.0f) > aG30 + aP3[a];
                    const bool i1 = fmaxf(ox1, 0.0f) * fmaxf(oy1, 0.0f) > aG31 + aP3[a];
                    ign[a] = ign[a] || i0 || i1;
                }
            }
        }
    }

    // --- single match scan for all 3 anchors (last-write-wins == max n) ---
    int bestA[NA] = {-1, -1, -1};
    {
        const int ij = (hy << 8) | wx;
        #pragma unroll
        for (int s = 0; s < 2; s++) {
            const int c = s_mcnt[s];
            for (int k = 0; k < c; k++) {
                const int pk = s_mpk[s*32 + k];
                if (((pk >> 6) & 0xFFFF) == ij) {
                    const int anc = pk >> 22;
                    const int n   = pk & 63;
                    if (anc == 0)      bestA[0] = max(bestA[0], n);
                    else if (anc == 1) bestA[1] = max(bestA[1], n);
                    else               bestA[2] = max(bestA[2], n);
                }
            }
        }
    }

    // --- per-anchor accumulation: 3 float channels + 2 ballot-counted ints ---
    // f0=box, f1=1.5*obj+0.5*noobj_bce, f2=cls
    float vals[3] = {0.0f, 0.0f, 0.0f};
    int np = 0, nn = 0;   // warp totals via popc (identical across lanes)
    #pragma unroll
    for (int a = 0; a < NA; a++) {
        const bool matched = bestA[a] >= 0;
        const float noobj = ign[a] ? 0.0f : 1.0f;

        // exact counts via ballots (replaces 2 float reduction channels)
        const unsigned bm = __ballot_sync(0xFFFFFFFFu, matched);
        const unsigned bn = __ballot_sync(0xFFFFFFFFu, !ign[a]);
        np += __popc(bm);
        nn += __popc(bn);

        // softplus: -log(sigmoid(x)) = log(1+e^-x); -log(1-sigmoid(x)) = x + log(1+e^-x)
        const float l = __logf(1.0f + __expf(-xo[a]));

        if (matched) {
            const int bestN = bestA[a];
            const float bceP1 = fminf(l, 100.0f);
            vals[1] += 1.5f * bceP1 + 0.5f * noobj * bceP1;
            // cls bce via same softplus identity (t selects branch)
            const float xCls = head[base0 + a * (6 * HW) + 5 * HW];
            const int   labN = labels[b * NB + bestN];
            const float lc = __logf(1.0f + __expf(-xCls));
            vals[2] += (labN == 0) ? fminf(lc, 100.0f)
                                   : fminf(xCls + lc, 100.0f);
            // ciou(pred, target); GT box re-loaded from gmem (rare path, L1/L2-hot)
            const float4 gb = ((const float4*)boxes)[b * NB + bestN];
            const float tx1 = gb.x - 0.5f*gb.z, ty1 = gb.y - 0.5f*gb.w;
            const float tx2 = gb.x + 0.5f*gb.z, ty2 = gb.y + 0.5f*gb.w;
            const float bw = px2[a] - px1[a], bh = py2[a] - py1[a];
            const float bx = 0.5f * (px1[a] + px2[a]);
            const float by = 0.5f * (py1[a] + py2[a]);
            const float imx = fmaxf(px1[a], tx1), imy = fmaxf(py1[a], ty1);
            const float iMx = fminf(px2[a], tx2), iMy = fminf(py2[a], ty2);
            const float iw = fmaxf(iMx - imx, 0.0f), ihh = fmaxf(iMy - imy, 0.0f);
            const float inter = iw * ihh;
            const float uni = bw * bh + gb.z * gb.w - inter;
            const float iou = inter / fmaxf(uni, 1e-6f);
            const float d   = fabsf(bx - gb.x) + fabsf(by - gb.y);
            const float ex1 = fminf(px1[a], tx1), ey1 = fminf(py1[a], ty1);
            const float ex2 = fmaxf(px2[a], tx2), ey2 = fmaxf(py2[a], ty2);
            const float cc  = fabsf(ex2 - ex1) + fabsf(ey2 - ey1);
            const float dis = d / fmaxf(cc, 1e-6f);
            const float a1  = atanf(bw / fmaxf(bh, 1e-6f));
            const float a2  = atanf(gb.z / fmaxf(gb.w, 1e-6f));
            const float PIc = 3.1415926f;
            const float vv  = (4.0f / (PIc * PIc)) * fabsf(a1 - a2);
            const float al  = vv / fmaxf(1.0f - iou + vv, 1e-6f);
            vals[0] += 1.0f - iou + dis + al * vv;
        } else {
            vals[1] += 0.5f * noobj * fminf(xo[a] + l, 100.0f);   // bce(p,0)
        }
    }

    // --- block reduction: 3 float channels (shuffle) + 2 int (lane0 only) ---
    #pragma unroll
    for (int off = 16; off > 0; off >>= 1) {
        #pragma unroll
        for (int j = 0; j < 3; j++)
            vals[j] += __shfl_down_sync(0xFFFFFFFFu, vals[j], off);
    }
    if (lane == 0) {
        #pragma unroll
        for (int j = 0; j < 3; j++) s_redF[warp][j] = vals[j];
        s_redI[warp][0] = np;
        s_redI[warp][1] = nn;
    }
    __syncthreads();
    if (warp == 0) {
        float r[3];
        #pragma unroll
        for (int j = 0; j < 3; j++) r[j] = (lane < 8) ? s_redF[lane][j] : 0.0f;
        #pragma unroll
        for (int off = 4; off > 0; off >>= 1) {
            #pragma unroll
            for (int j = 0; j < 3; j++)
                r[j] += __shfl_down_sync(0xFFFFFFFFu, r[j], off);
        }
        if (lane == 0) {
            int npos_b = 0, nobj_b = 0;
            #pragma unroll
            for (int w = 0; w < 8; w++) { npos_b += s_redI[w][0]; nobj_b += s_redI[w][1]; }
            #pragma unroll
            for (int j = 0; j < 3; j++) atomicAdd(&g_accF[j], (double)r[j]);
            atomicAdd(&g_npos, npos_b);
            atomicAdd(&g_nobj, nobj_b);
            __threadfence();
            const int old = atomicAdd(&g_count, 1);
            if (old == TOTAL_BLOCKS - 1) {
                __threadfence();
                const double s0 = g_accF[0], s1 = g_accF[1], s2 = g_accF[2];
                const double npos = (double)g_npos;
                const double nobj = (double)g_nobj;
                out[0] = (float)(0.05 * s0 / npos);
                out[1] = (float)(s1 / (npos + nobj) + 0.5 * s2 / (npos * (double)NCLS));
                g_accF[0] = 0.0; g_accF[1] = 0.0; g_accF[2] = 0.0;
                g_npos = 0; g_nobj = 0;
                g_count = 0;   // reset for next graph replay
            }
        }
    }
}

extern "C" void kernel_launch(void* const* d_in, const int* in_sizes, int n_in,
                              void* d_out, int out_size) {
    const float* head    = (const float*)d_in[0];
    const float* boxes   = (const float*)d_in[1];
    const float* anchors = (const float*)d_in[2];
    const int*   labels  = (const int*)d_in[3];
    (void)in_sizes; (void)n_in; (void)out_size;

    dim3 grid(TILES, BATCH);
    yolo_fused_kernel<<<grid, THREADS>>>(head, boxes, anchors, labels, (float*)d_out);
}